// round 14
// baseline (speedup 1.0000x reference)
#include <cuda_runtime.h>
#include <cuda_bf16.h>
#include <cstdint>

// ---------------- shapes ----------------
#define BB    16
#define CC    128
#define HIDD  256
#define PP    6400
#define NGG   8
#define EPSV  1e-5f

#define NPAD  6724      // 82*82
#define NPADT 6784      // 53 tiles * 128
#define GUARD 128
#define XROWS 7040      // GUARD + NPADT + GUARD

// smem tile geometry: [128 rows][136 bf16] = 272 B/row (conflict-free ldmatrix)
#define TROW   272
#define TILEB  34816    // 128*272

// conv halo window: rows p0-83 .. p0+210
#define XW_ROWS 294
#define XW_BYTES (XW_ROWS * TROW)      // 79968
#define SMEM_CONV (2 * XW_BYTES)       // 159936 (xh + xl windows only)
#define SMEM_G2   (2 * TILEB)          // 69632  (Bhi + Blo)

#define NT 512          // threads per MMA CTA (16 warps, 4x4 warp grid)

// ---------------- device scratch (static; allocation-free) ----------------
__device__ __align__(16) float g_s[(size_t)BB * CC * PP];
__device__ __align__(16) float g_y[(size_t)BB * CC * PP];
__device__ __align__(16) float g_h[(size_t)BB * NPADT * HIDD];   // f32 [b][pos][256]

__device__ uint4 g_xp_hi[(size_t)BB * XROWS * 16];   // [b][row][128 ci] bf16, 256B rows
__device__ uint4 g_xp_lo[(size_t)BB * XROWS * 16];

// fragment-packed weights: [tile16][ks][lane] -> one uint4 = {a0,a1,a2,a3}
__device__ uint4 g_wfc[9 * 2 * 8 * 8 * 32];    // conv: [tap][part][mt8][ks8][lane]
__device__ uint4 g_wf1[3 * 2 * 16 * 8 * 32];   // w1:   [e][part][mt16][ks8][lane]
__device__ uint4 g_wf2[3 * 2 * 8 * 16 * 32];   // w2:   [e][part][mt8][ks16][lane]

__device__ float g_bn_sum[CC], g_bn_sq[CC];
__device__ float g_bn_scale[CC], g_bn_shift[CC];
__device__ float g_gn1_sum[BB * NGG], g_gn1_sq[BB * NGG];
__device__ float g_gn1_mr[BB * NGG * 2];
__device__ float g_gn2_sum[BB * NGG], g_gn2_sq[BB * NGG];
__device__ float g_gn2_mr[BB * NGG * 2];

// ---------------- helpers ----------------
__device__ __forceinline__ uint32_t smem_u32(const void* p) {
    uint32_t a;
    asm("{ .reg .u64 t; cvta.to.shared.u64 t, %1; cvt.u32.u64 %0, t; }" : "=r"(a) : "l"(p));
    return a;
}

__device__ __forceinline__ void mma16816(float* d, const uint32_t* a, uint32_t b0, uint32_t b1) {
    asm volatile(
        "mma.sync.aligned.m16n8k16.row.col.f32.bf16.bf16.f32 "
        "{%0,%1,%2,%3}, {%4,%5,%6,%7}, {%8,%9}, {%0,%1,%2,%3};"
        : "+f"(d[0]), "+f"(d[1]), "+f"(d[2]), "+f"(d[3])
        : "r"(a[0]), "r"(a[1]), "r"(a[2]), "r"(a[3]), "r"(b0), "r"(b1));
}

// FMA-only sigmoid (no MUFU)
__device__ __forceinline__ float fast_sigmoid(float t) {
    float z = -t * 1.442695041f;
    z = fminf(fmaxf(z, -60.f), 60.f);
    float fl = floorf(z);
    float f = z - fl;
    float p = 1.5403530e-4f;
    p = fmaf(p, f, 1.3333558e-3f);
    p = fmaf(p, f, 9.6181291e-3f);
    p = fmaf(p, f, 5.5504109e-2f);
    p = fmaf(p, f, 2.4022651e-1f);
    p = fmaf(p, f, 6.9314718e-1f);
    float two_f = fmaf(p, f, 1.0f);
    float ex = __int_as_float((127 + (int)fl) << 23) * two_f;   // exp(-t)
    float d = 1.f + ex;
    float r = __int_as_float(0x7EF311C3 - __float_as_int(d));
    r = r * (2.f - d * r);
    r = r * (2.f - d * r);
    r = r * (2.f - d * r);
    return r;
}

// stage one [128 rows][256B used] tile into smem [128][272B] via cp.async (NT threads)
__device__ __forceinline__ void stage_cp(uint32_t s_dst, const char* src, int rowStride, int tid) {
#pragma unroll
    for (int it = 0; it < 4; it++) {
        int idx = it * NT + tid;           // 0..2047
        int r = idx >> 4, c = idx & 15;
        uint32_t d = s_dst + (uint32_t)(r * TROW + c * 16);
        const char* s = src + (size_t)r * rowStride + c * 16;
        asm volatile("cp.async.cg.shared.global [%0], [%1], 16;" :: "r"(d), "l"(s));
    }
}

__device__ __forceinline__ uint32_t pack2(float a, float b, int part) {
    __nv_bfloat16 ha = __float2bfloat16(a), hb = __float2bfloat16(b);
    if (part) {
        ha = __float2bfloat16(a - __bfloat162float(ha));
        hb = __float2bfloat16(b - __bfloat162float(hb));
    }
    return (uint32_t)*(uint16_t*)&ha | ((uint32_t)*(uint16_t*)&hb << 16);
}

// ============================================================================
// k_prep: pack_x (3200 blocks) + zero_xp (448) + pack_w frag-order (336) + zero (1)
// ============================================================================
__global__ __launch_bounds__(256) void k_prep(const float* __restrict__ x,
                                              const float* __restrict__ w,
                                              const float* __restrict__ w1,
                                              const float* __restrict__ w2) {
    __shared__ float t[128 * 33];
    const int bi = blockIdx.x, tid = threadIdx.x;

    if (bi < 3200) {               // ---- pack_x ----
        int b = bi / 200, p0 = (bi - b * 200) * 32;
        const float* xb = x + (size_t)b * CC * PP;
#pragma unroll
        for (int i = 0; i < 16; i++) {
            int lin = i * 256 + tid;
            int c = lin >> 5, px = lin & 31;
            t[c * 33 + px] = xb[(size_t)c * PP + p0 + px];
        }
        __syncthreads();
        __nv_bfloat16* hiA = (__nv_bfloat16*)g_xp_hi;
        __nv_bfloat16* loA = (__nv_bfloat16*)g_xp_lo;
#pragma unroll
        for (int i = 0; i < 16; i++) {
            int lin = i * 256 + tid;
            int c = tid & 127, px = (lin >> 7) & 31;
            float v = t[c * 33 + px];
            int p = p0 + px;
            int r = p / 80, q = p - r * 80;
            int pos = (r + 1) * 82 + (q + 1);
            size_t a = ((size_t)b * XROWS + GUARD + pos) * 128 + c;
            __nv_bfloat16 hi = __float2bfloat16(v);
            hiA[a] = hi;
            loA[a] = __float2bfloat16(v - __bfloat162float(hi));
        }
    } else if (bi < 3648) {        // ---- zero_xp ----
        int zbi = bi - 3200;
        int b = zbi / 28;
        int ro = (zbi - b * 28) * 256 + tid;
        if (ro >= XROWS) return;
        int pos = ro - GUARD;
        bool interior = false;
        if (pos >= 0 && pos < NPAD) {
            int r = pos / 82, q = pos - r * 82;
            interior = (r >= 1 && r <= 80 && q >= 1 && q <= 80);
        }
        if (!interior) {
            uint4 z = make_uint4(0, 0, 0, 0);
            size_t base = ((size_t)b * XROWS + ro) * 16;
#pragma unroll
            for (int j = 0; j < 16; j++) { g_xp_hi[base + j] = z; g_xp_lo[base + j] = z; }
        }
    } else if (bi < 3984) {        // ---- pack_w (fragment order) ----
        int idx = (bi - 3648) * 256 + tid;   // 0..86015
        if (idx < 36864) {                   // conv weights
            int lane = idx & 31;
            int ks = (idx >> 5) & 7, mt = (idx >> 8) & 7;
            int part = (idx >> 11) & 1, tap = idx >> 12;
            int r0 = mt * 16 + (lane >> 2), r1 = r0 + 8;
            int k0 = ks * 16 + (lane & 3) * 2;
#define WCV(r, k) w[((size_t)(r) * 128 + (k)) * 9 + tap]
            uint4 o;
            o.x = pack2(WCV(r0, k0),     WCV(r0, k0 + 1), part);
            o.y = pack2(WCV(r1, k0),     WCV(r1, k0 + 1), part);
            o.z = pack2(WCV(r0, k0 + 8), WCV(r0, k0 + 9), part);
            o.w = pack2(WCV(r1, k0 + 8), WCV(r1, k0 + 9), part);
#undef WCV
            g_wfc[idx] = o;
        } else if (idx < 61440) {            // w1
            int j = idx - 36864;
            int lane = j & 31;
            int ks = (j >> 5) & 7, mt = (j >> 8) & 15;
            int part = (j >> 12) & 1, e = j >> 13;
            int r0 = mt * 16 + (lane >> 2), r1 = r0 + 8;
            int k0 = ks * 16 + (lane & 3) * 2;
            const float* wb = w1 + (size_t)e * 32768;
#define W1V(r, k) wb[(size_t)(r) * 128 + (k)]
            uint4 o;
            o.x = pack2(W1V(r0, k0),     W1V(r0, k0 + 1), part);
            o.y = pack2(W1V(r1, k0),     W1V(r1, k0 + 1), part);
            o.z = pack2(W1V(r0, k0 + 8), W1V(r0, k0 + 9), part);
            o.w = pack2(W1V(r1, k0 + 8), W1V(r1, k0 + 9), part);
#undef W1V
            g_wf1[j] = o;
        } else {                             // w2
            int j = idx - 61440;
            int lane = j & 31;
            int kst = (j >> 5) & 15, mt = (j >> 9) & 7;
            int part = (j >> 12) & 1, e = j >> 13;
            int r0 = mt * 16 + (lane >> 2), r1 = r0 + 8;
            int k0 = kst * 16 + (lane & 3) * 2;
            const float* wb = w2 + (size_t)e * 32768;
#define W2V(r, k) wb[(size_t)(r) * 256 + (k)]
            uint4 o;
            o.x = pack2(W2V(r0, k0),     W2V(r0, k0 + 1), part);
            o.y = pack2(W2V(r1, k0),     W2V(r1, k0 + 1), part);
            o.z = pack2(W2V(r0, k0 + 8), W2V(r0, k0 + 9), part);
            o.w = pack2(W2V(r1, k0 + 8), W2V(r1, k0 + 9), part);
#undef W2V
            g_wf2[j] = o;
        }
    } else {                       // ---- zero stats ----
        if (tid < CC) { g_bn_sum[tid] = 0.f; g_bn_sq[tid] = 0.f; }
        if (tid < BB * NGG) {
            g_gn1_sum[tid] = 0.f; g_gn1_sq[tid] = 0.f;
            g_gn2_sum[tid] = 0.f; g_gn2_sq[tid] = 0.f;
        }
    }
}

// fin_bn + fin_gn1
__global__ void k_fin1(const float* __restrict__ gamma, const float* __restrict__ beta) {
    int t = threadIdx.x;   // 256
    if (t < 128) {
        const float inv = 1.f / (float)(BB * PP);
        float m = g_bn_sum[t] * inv;
        float v = g_bn_sq[t] * inv - m * m;
        float sc = gamma[t] * rsqrtf(v + EPSV);
        g_bn_scale[t] = sc;
        g_bn_shift[t] = beta[t] - m * sc;
    } else {
        int u = t - 128;
        const float inv = 1.f / (float)((HIDD / NGG) * PP);
        float m = g_gn1_sum[u] * inv;
        float v = g_gn1_sq[u] * inv - m * m;
        g_gn1_mr[2 * u] = m;
        g_gn1_mr[2 * u + 1] = rsqrtf(v + EPSV);
    }
}

__global__ void k_fin_gn2() {
    int t = threadIdx.x;
    const float inv = 1.f / (float)((CC / NGG) * PP);
    float m = g_gn2_sum[t] * inv;
    float v = g_gn2_sq[t] * inv - m * m;
    g_gn2_mr[2 * t] = m;
    g_gn2_mr[2 * t + 1] = rsqrtf(v + EPSV);
}

// ============================================================================
// merged conv3x3 + gemm1, NT=512 threads, 4x4 warp grid, warp tile 32x32.
// A fragments are prefetched one step ahead (global->reg double buffer).
// ============================================================================
__device__ __forceinline__ void conv_body(char* smem, float* ssum, float* ssq,
                                          const int tid, const int b, const int p0) {
    const int wid = tid >> 5, l = tid & 31;
    const uint32_t sbase = smem_u32(smem);
    const int warp_m0 = (wid & 3) * 32;
    const int warp_n0 = (wid >> 2) * 32;
    const int quad = l >> 2, qt = l & 3;
    const int mtb = (wid & 3) * 2;

    uint32_t boffr[2];
    {
        int rowB = ((l >> 4) << 3) + (l & 7);
        int colB = (l >> 3) & 1;
#pragma unroll
        for (int g = 0; g < 2; g++)
            boffr[g] = (uint32_t)((warp_n0 + g * 16 + rowB) * TROW + colB * 16);
    }

    float d[2][4][4];
#pragma unroll
    for (int i = 0; i < 2; i++)
#pragma unroll
        for (int j = 0; j < 4; j++)
#pragma unroll
            for (int k = 0; k < 4; k++) d[i][j][k] = 0.f;

    // stage x halo windows (once)
    {
        const size_t g0 = (size_t)b * XROWS + GUARD + p0 - 83;
        const char* xh = (const char*)g_xp_hi + g0 * 256;
        const char* xl = (const char*)g_xp_lo + g0 * 256;
        for (int i = tid; i < XW_ROWS * 16; i += NT) {
            int r = i >> 4, c = i & 15;
            uint32_t dof = (uint32_t)(r * TROW + c * 16);
            const size_t sof = (size_t)r * 256 + c * 16;
            asm volatile("cp.async.cg.shared.global [%0], [%1], 16;"
                         :: "r"(sbase + dof), "l"(xh + sof));
            asm volatile("cp.async.cg.shared.global [%0], [%1], 16;"
                         :: "r"(sbase + XW_BYTES + dof), "l"(xl + sof));
        }
        asm volatile("cp.async.commit_group;" ::: "memory");
        asm volatile("cp.async.wait_group 0;" ::: "memory");
    }
    if (tid < 128) { ssum[tid] = 0.f; ssq[tid] = 0.f; }
    __syncthreads();

    // flattened 72-step mainloop (tap = idx>>3, ks = idx&7), A prefetched +1
    const uint4* wbase = g_wfc + l;
    uint4 ahc[2], alc[2];
    ahc[0] = wbase[(mtb * 8) * 32];
    ahc[1] = wbase[((mtb + 1) * 8) * 32];
    alc[0] = wbase[2048 + (mtb * 8) * 32];
    alc[1] = wbase[2048 + ((mtb + 1) * 8) * 32];

#pragma unroll 4
    for (int idx = 0; idx < 72; idx++) {
        const int tap = idx >> 3, ks = idx & 7;
        const int kh = tap / 3, kw = tap - kh * 3;
        const uint32_t winbase = (uint32_t)(((kh - 1) * 82 + (kw - 1) + 83) * TROW);
        const uint32_t xhb = sbase + winbase;
        const uint32_t xlb = sbase + XW_BYTES + winbase;

        uint4 ahn[2], aln[2];
        if (idx < 71) {
            const int t2 = (idx + 1) >> 3, k2 = (idx + 1) & 7;
            const uint4* w2p = wbase + (size_t)(t2 * 2) * 2048;
            ahn[0] = w2p[(mtb * 8 + k2) * 32];
            ahn[1] = w2p[((mtb + 1) * 8 + k2) * 32];
            aln[0] = w2p[2048 + (mtb * 8 + k2) * 32];
            aln[1] = w2p[2048 + ((mtb + 1) * 8 + k2) * 32];
        }

        uint32_t bh[2][4], bl[2][4];
#pragma unroll
        for (int g = 0; g < 2; g++) {
            asm volatile("ldmatrix.sync.aligned.m8n8.x4.shared.b16 {%0,%1,%2,%3}, [%4];"
                : "=r"(bh[g][0]), "=r"(bh[g][1]), "=r"(bh[g][2]), "=r"(bh[g][3])
                : "r"(xhb + boffr[g] + ks * 32));
            asm volatile("ldmatrix.sync.aligned.m8n8.x4.shared.b16 {%0,%1,%2,%3}, [%4];"
                : "=r"(bl[g][0]), "=r"(bl[g][1]), "=r"(bl[g][2]), "=r"(bl[g][3])
                : "r"(xlb + boffr[g] + ks * 32));
        }
#pragma unroll
        for (int i = 0; i < 2; i++) {
            const uint32_t* ahp = (const uint32_t*)&ahc[i];
            const uint32_t* alp = (const uint32_t*)&alc[i];
#pragma unroll
            for (int j = 0; j < 4; j++) {
                int g = j >> 1, s = (j & 1) * 2;
                mma16816(d[i][j], ahp, bh[g][s], bh[g][s + 1]);
                mma16816(d[i][j], ahp, bl[g][s], bl[g][s + 1]);
                mma16816(d[i][j], alp, bh[g][s], bh[g][s + 1]);
            }
        }
        if (idx < 71) {
            ahc[0] = ahn[0]; ahc[1] = ahn[1];
            alc[0] = aln[0]; alc[1] = aln[1];
        }
    }

    // epilogue: write g_s (interior only) + BN partial stats
    float* dst = g_s + (size_t)b * CC * PP;
#pragma unroll
    for (int i = 0; i < 2; i++)
#pragma unroll
        for (int rh = 0; rh < 2; rh++) {
            int m = warp_m0 + 16 * i + quad + rh * 8;
            float ps = 0.f, pq = 0.f;
#pragma unroll
            for (int j = 0; j < 4; j++) {
                float v0 = d[i][j][rh * 2], v1 = d[i][j][rh * 2 + 1];
                int n = warp_n0 + 8 * j + 2 * qt;
                int pos = p0 + n;
                int r = pos / 82, q = pos - r * 82;
                bool in0 = (pos < NPAD) && r >= 1 && r <= 80 && q >= 1 && q <= 80;
                bool in1 = (pos + 1 < NPAD) && r >= 1 && r <= 80 && (q + 1) >= 1 && (q + 1) <= 80;
                if (in0) { dst[(size_t)m * PP + (r - 1) * 80 + (q - 1)] = v0; ps += v0; pq += v0 * v0; }
                if (in1) { dst[(size_t)m * PP + (r - 1) * 80 + q] = v1; ps += v1; pq += v1 * v1; }
            }
            ps += __shfl_down_sync(0xffffffffu, ps, 2);
            pq += __shfl_down_sync(0xffffffffu, pq, 2);
            ps += __shfl_down_sync(0xffffffffu, ps, 1);
            pq += __shfl_down_sync(0xffffffffu, pq, 1);
            if (qt == 0) { atomicAdd(&ssum[m], ps); atomicAdd(&ssq[m], pq); }
        }

    __syncthreads();
    if (tid < 128) {
        atomicAdd(&g_bn_sum[tid], ssum[tid]);
        atomicAdd(&g_bn_sq[tid], ssq[tid]);
    }
}

__device__ __forceinline__ void gemm1_body(char* smem, float* ssum, float* ssq,
                                           const int tid, const int b, const int e,
                                           const int p0, const int m0) {
    const int wid = tid >> 5, l = tid & 31;
    const uint32_t sbase = smem_u32(smem);
    const int warp_m0 = (wid & 3) * 32;
    const int warp_n0 = (wid >> 2) * 32;
    const int quad = l >> 2, qt = l & 3;
    const int mtb = (m0 >> 4) + (wid & 3) * 2;

    uint32_t boff[2];
    {
        int rowB = ((l >> 4) << 3) + (l & 7);
        int colB = (l >> 3) & 1;
#pragma unroll
        for (int g = 0; g < 2; g++)
            boff[g] = (uint32_t)((warp_n0 + g * 16 + rowB) * TROW + colB * 16);
    }

    float d[2][4][4];
#pragma unroll
    for (int i = 0; i < 2; i++)
#pragma unroll
        for (int j = 0; j < 4; j++)
#pragma unroll
            for (int k = 0; k < 4; k++) d[i][j][k] = 0.f;

    // stage B tiles (xh, xl) once
    {
        const char* bsx_hi = (const char*)g_xp_hi + ((size_t)b * XROWS + GUARD + p0) * 256;
        const char* bsx_lo = (const char*)g_xp_lo + ((size_t)b * XROWS + GUARD + p0) * 256;
        stage_cp(sbase, bsx_hi, 256, tid);
        stage_cp(sbase + TILEB, bsx_lo, 256, tid);
        asm volatile("cp.async.commit_group;" ::: "memory");
    }

    const uint4* wfh = g_wf1 + (size_t)(e * 2) * 4096 + l;
    const uint4* wfl = wfh + 4096;

    uint4 ahc[2], alc[2];
    ahc[0] = wfh[(mtb * 8) * 32];
    ahc[1] = wfh[((mtb + 1) * 8) * 32];
    alc[0] = wfl[(mtb * 8) * 32];
    alc[1] = wfl[((mtb + 1) * 8) * 32];

    asm volatile("cp.async.wait_group 0;" ::: "memory");
    if (tid < 128) { ssum[tid] = 0.f; ssq[tid] = 0.f; }
    __syncthreads();

#pragma unroll
    for (int ks = 0; ks < 8; ks++) {
        uint4 ahn[2], aln[2];
        if (ks < 7) {
            ahn[0] = wfh[(mtb * 8 + ks + 1) * 32];
            ahn[1] = wfh[((mtb + 1) * 8 + ks + 1) * 32];
            aln[0] = wfl[(mtb * 8 + ks + 1) * 32];
            aln[1] = wfl[((mtb + 1) * 8 + ks + 1) * 32];
        }

        uint32_t bh[2][4], bl[2][4];
#pragma unroll
        for (int g = 0; g < 2; g++) {
            asm volatile("ldmatrix.sync.aligned.m8n8.x4.shared.b16 {%0,%1,%2,%3}, [%4];"
                : "=r"(bh[g][0]), "=r"(bh[g][1]), "=r"(bh[g][2]), "=r"(bh[g][3])
                : "r"(sbase + boff[g] + ks * 32));
            asm volatile("ldmatrix.sync.aligned.m8n8.x4.shared.b16 {%0,%1,%2,%3}, [%4];"
                : "=r"(bl[g][0]), "=r"(bl[g][1]), "=r"(bl[g][2]), "=r"(bl[g][3])
                : "r"(sbase + TILEB + boff[g] + ks * 32));
        }
#pragma unroll
        for (int i = 0; i < 2; i++) {
            const uint32_t* ahp = (const uint32_t*)&ahc[i];
            const uint32_t* alp = (const uint32_t*)&alc[i];
#pragma unroll
            for (int j = 0; j < 4; j++) {
                int g = j >> 1, s = (j & 1) * 2;
                mma16816(d[i][j], ahp, bh[g][s], bh[g][s + 1]);
                mma16816(d[i][j], ahp, bl[g][s], bl[g][s + 1]);
                mma16816(d[i][j], alp, bh[g][s], bh[g][s + 1]);
            }
        }
        if (ks < 7) {
            ahc[0] = ahn[0]; ahc[1] = ahn[1];
            alc[0] = aln[0]; alc[1] = aln[1];
        }
    }

    // epilogue: write h f32 + GN1 stats (interior masked)
    float* hb = g_h + (size_t)b * NPADT * 256;
#pragma unroll
    for (int i = 0; i < 2; i++)
#pragma unroll
        for (int rh = 0; rh < 2; rh++) {
            int m = warp_m0 + 16 * i + quad + rh * 8;
            float ps = 0.f, pq = 0.f;
#pragma unroll
            for (int j = 0; j < 4; j++) {
                float v0 = d[i][j][rh * 2], v1 = d[i][j][rh * 2 + 1];
                int n = warp_n0 + 8 * j + 2 * qt;
                int pos = p0 + n;
                hb[(size_t)pos * 256 + m0 + m] = v0;
                hb[(size_t)(pos + 1) * 256 + m0 + m] = v1;
                int r = pos / 82, q = pos - r * 82;
                bool in0 = (pos < NPAD) && r >= 1 && r <= 80 && q >= 1 && q <= 80;
                bool in1 = (pos + 1 < NPAD) && r >= 1 && r <= 80 && (q + 1) >= 1 && (q + 1) <= 80;
                if (in0) { ps += v0; pq += v0 * v0; }
                if (in1) { ps += v1; pq += v1 * v1; }
            }
            ps += __shfl_down_sync(0xffffffffu, ps, 2);
            pq += __shfl_down_sync(0xffffffffu, pq, 2);
            ps += __shfl_down_sync(0xffffffffu, ps, 1);
            pq += __shfl_down_sync(0xffffffffu, pq, 1);
            if (qt == 0) { atomicAdd(&ssum[m], ps); atomicAdd(&ssq[m], pq); }
        }

    __syncthreads();
    if (tid < 128) {
        atomicAdd(&g_gn1_sum[b * NGG + ((m0 + tid) >> 5)], ssum[tid]);
        atomicAdd(&g_gn1_sq[b * NGG + ((m0 + tid) >> 5)], ssq[tid]);
    }
}

__global__ __launch_bounds__(NT) void k_convg1(const int* __restrict__ indices) {
    extern __shared__ __align__(16) char smem[];
    __shared__ float ssum[128], ssq[128];
    const int tid = threadIdx.x;
    const int b = blockIdx.z;
    const int p0 = blockIdx.x * 128;
    if (blockIdx.y == 0) {
        conv_body(smem, ssum, ssq, tid, b, p0);
    } else {
        int id = indices[b];
        if (id == 0) return;
        gemm1_body(smem, ssum, ssq, tid, b, id - 1, p0, (blockIdx.y - 1) * 128);
    }
}

// ============================================================================
// k_gemm2: y = w2 @ silu(GN1(h)); A-frags via LDG (prefetched); B built in smem
// ============================================================================
__global__ __launch_bounds__(NT) void k_gemm2(const int* __restrict__ indices,
                                              const float* __restrict__ g1,
                                              const float* __restrict__ b1) {
    extern __shared__ __align__(16) char smem[];
    __shared__ float ssum[128], ssq[128];
    __shared__ float sa[256], sc[256];

    const int tid = threadIdx.x, wid = tid >> 5, l = tid & 31;
    const int b = blockIdx.z;
    int id = indices[b];
    if (id == 0) return;
    const int e = id - 1;
    const int p0 = blockIdx.x * 128;

    if (tid < 128) { ssum[tid] = 0.f; ssq[tid] = 0.f; }

    const uint32_t sbase = smem_u32(smem);
    const int warp_m0 = (wid & 3) * 32;
    const int warp_n0 = (wid >> 2) * 32;
    const int quad = l >> 2, qt = l & 3;
    const int mtb = (wid & 3) * 2;

    uint32_t boff[2];
    {
        int rowB = ((l >> 4) << 3) + (l & 7);
        int colB = (l >> 3) & 1;
#pragma unroll
        for (int g = 0; g < 2; g++)
            boff[g] = (uint32_t)((warp_n0 + g * 16 + rowB) * TROW + colB * 16);
    }

    // GN1 affine coefficients
    if (tid < 256) {
        int k = tid;
        int gg = k >> 5;
        float mean = g_gn1_mr[(b * NGG + gg) * 2];
        float rstd = g_gn1_mr[(b * NGG + gg) * 2 + 1];
        float a = rstd * g1[e * 256 + k];
        sa[k] = a;
        sc[k] = b1[e * 256 + k] - mean * a;
    }
    __syncthreads();

    float d[2][4][4];
#pragma unroll
    for (int i = 0; i < 2; i++)
#pragma unroll
        for (int j = 0; j < 4; j++)
#pragma unroll
            for (int k = 0; k < 4; k++) d[i][j][k] = 0.f;

    const float* hb = g_h + (size_t)b * NPADT * 256;
    const uint32_t sBhi = sbase;
    const uint32_t sBlo = sbase + TILEB;
    const uint4* wfh = g_wf2 + (size_t)(e * 2) * 4096 + l;
    const uint4* wfl = wfh + 4096;

    // preload kstot = 0 fragments
    uint4 ahc[2], alc[2];
    ahc[0] = wfh[(mtb * 16) * 32];
    ahc[1] = wfh[((mtb + 1) * 16) * 32];
    alc[0] = wfl[(mtb * 16) * 32];
    alc[1] = wfl[((mtb + 1) * 16) * 32];

    for (int kh = 0; kh < 2; kh++) {
        // build B_hi/B_lo: affine + silu + split (A-frags for this kh already in regs)
#pragma unroll
        for (int it = 0; it < 8; it++) {
            int j = it * NT + tid;         // 0..4095 float4 jobs
            int row = j >> 5, c4 = j & 31;
            float4 v = *(const float4*)(hb + (size_t)(p0 + row) * 256 + kh * 128 + c4 * 4);
            int k0 = kh * 128 + c4 * 4;
            float s0, s1, s2, s3, t;
            t = fmaf(v.x, sa[k0],     sc[k0]);     s0 = t * fast_sigmoid(t);
            t = fmaf(v.y, sa[k0 + 1], sc[k0 + 1]); s1 = t * fast_sigmoid(t);
            t = fmaf(v.z, sa[k0 + 2], sc[k0 + 2]); s2 = t * fast_sigmoid(t);
            t = fmaf(v.w, sa[k0 + 3], sc[k0 + 3]); s3 = t * fast_sigmoid(t);
            __nv_bfloat16 h0 = __float2bfloat16(s0), h1 = __float2bfloat16(s1);
            __nv_bfloat16 h2 = __float2bfloat16(s2), h3 = __float2bfloat16(s3);
            __nv_bfloat16 l0 = __float2bfloat16(s0 - __bfloat162float(h0));
            __nv_bfloat16 l1 = __float2bfloat16(s1 - __bfloat162float(h1));
            __nv_bfloat16 l2 = __float2bfloat16(s2 - __bfloat162float(h2));
            __nv_bfloat16 l3 = __float2bfloat16(s3 - __bfloat162float(h3));
            uint32_t hp0 = (uint32_t)*(uint16_t*)&h0 | ((uint32_t)*(uint16_t*)&h1 << 16);
            uint32_t hp1 = (uint32_t)*(uint16_t*)&h2 | ((uint32_t)*(uint16_t*)&h3 << 16);
            uint32_t lp0 = (uint32_t)*(uint16_t*)&l0 | ((uint32_t)*(uint16_t*)&l1 << 16);
            uint32_t lp1 = (uint32_t)*(uint16_t*)&l2 | ((uint32_t)*(uint16_t*)&l3 << 16);
            uint32_t off = (uint32_t)(row * TROW + c4 * 8);
            asm volatile("st.shared.v2.b32 [%0], {%1,%2};" :: "r"(sBhi + off), "r"(hp0), "r"(hp1));
            asm volatile("st.shared.v2.b32 [%0], {%1,%2};" :: "r"(sBlo + off), "r"(lp0), "r"(lp1));
        }
        __syncthreads();

#pragma unroll
        for (int ks = 0; ks < 8; ks++) {
            const int kstot = kh * 8 + ks;
            uint4 ahn[2], aln[2];
            if (kstot < 15) {
                ahn[0] = wfh[(mtb * 16 + kstot + 1) * 32];
                ahn[1] = wfh[((mtb + 1) * 16 + kstot + 1) * 32];
                aln[0] = wfl[(mtb * 16 + kstot + 1) * 32];
                aln[1] = wfl[((mtb + 1) * 16 + kstot + 1) * 32];
            }

            uint32_t bh[2][4], bl[2][4];
#pragma unroll
            for (int g = 0; g < 2; g++) {
                asm volatile("ldmatrix.sync.aligned.m8n8.x4.shared.b16 {%0,%1,%2,%3}, [%4];"
                    : "=r"(bh[g][0]), "=r"(bh[g][1]), "=r"(bh[g][2]), "=r"(bh[g][3])
                    : "r"(sBhi + boff[g] + ks * 32));
                asm volatile("ldmatrix.sync.aligned.m8n8.x4.shared.b16 {%0,%1,%2,%3}, [%4];"
                    : "=r"(bl[g][0]), "=r"(bl[g][1]), "=r"(bl[g][2]), "=r"(bl[g][3])
                    : "r"(sBlo + boff[g] + ks * 32));
            }
#pragma unroll
            for (int i = 0; i < 2; i++) {
                const uint32_t* ahp = (const uint32_t*)&ahc[i];
                const uint32_t* alp = (const uint32_t*)&alc[i];
#pragma unroll
                for (int j = 0; j < 4; j++) {
                    int g = j >> 1, s = (j & 1) * 2;
                    mma16816(d[i][j], ahp, bh[g][s], bh[g][s + 1]);
                    mma16816(d[i][j], ahp, bl[g][s], bl[g][s + 1]);
                    mma16816(d[i][j], alp, bh[g][s], bh[g][s + 1]);
                }
            }
            if (kstot < 15) {
                ahc[0] = ahn[0]; ahc[1] = ahn[1];
                alc[0] = aln[0]; alc[1] = aln[1];
            }
        }
        __syncthreads();
    }

    // epilogue: write g_y (interior only) + GN2 stats
    float* dst = g_y + (size_t)b * CC * PP;
#pragma unroll
    for (int i = 0; i < 2; i++)
#pragma unroll
        for (int rh = 0; rh < 2; rh++) {
            int m = warp_m0 + 16 * i + quad + rh * 8;
            float ps = 0.f, pq = 0.f;
#pragma unroll
            for (int j = 0; j < 4; j++) {
                float v0 = d[i][j][rh * 2], v1 = d[i][j][rh * 2 + 1];
                int n = warp_n0 + 8 * j + 2 * qt;
                int pos = p0 + n;
                int r = pos / 82, q = pos - r * 82;
                bool in0 = (pos < NPAD) && r >= 1 && r <= 80 && q >= 1 && q <= 80;
                bool in1 = (pos + 1 < NPAD) && r >= 1 && r <= 80 && (q + 1) >= 1 && (q + 1) <= 80;
                if (in0) { dst[(size_t)m * PP + (r - 1) * 80 + (q - 1)] = v0; ps += v0; pq += v0 * v0; }
                if (in1) { dst[(size_t)m * PP + (r - 1) * 80 + q] = v1; ps += v1; pq += v1 * v1; }
            }
            ps += __shfl_down_sync(0xffffffffu, ps, 2);
            pq += __shfl_down_sync(0xffffffffu, pq, 2);
            ps += __shfl_down_sync(0xffffffffu, ps, 1);
            pq += __shfl_down_sync(0xffffffffu, pq, 1);
            if (qt == 0) { atomicAdd(&ssum[m], ps); atomicAdd(&ssq[m], pq); }
        }

    __syncthreads();
    if (tid < 128) {
        atomicAdd(&g_gn2_sum[b * NGG + (tid >> 4)], ssum[tid]);
        atomicAdd(&g_gn2_sq[b * NGG + (tid >> 4)], ssq[tid]);
    }
}

// ---------------- combine ----------------
__global__ __launch_bounds__(256) void k_combine(const float* __restrict__ x,
                                                 const float* __restrict__ weights,
                                                 const int* __restrict__ indices,
                                                 const float* __restrict__ g2,
                                                 const float* __restrict__ b2,
                                                 float* __restrict__ out) {
    const int blk = blockIdx.x;
    const int b = blk >> 7, c = blk & 127;
    const int idx = indices[b];
    const float wb = weights[b];
    const float sc = g_bn_scale[c], sh = g_bn_shift[c];

    float a2, c2;
    if (idx > 0) {
        int e = idx - 1;
        int g = c >> 4;
        float mean = g_gn2_mr[(b * NGG + g) * 2];
        float rstd = g_gn2_mr[(b * NGG + g) * 2 + 1];
        float ga = rstd * g2[e * CC + c];
        a2 = ga * wb;
        c2 = (b2[e * CC + c] - mean * ga) * wb;
    } else {
        a2 = wb;
        c2 = 0.f;
    }

    const size_t base = ((size_t)b * CC + c) * PP;
    const float4* sp = (const float4*)(g_s + base);
    const float4* rp = (idx > 0) ? (const float4*)(g_y + base) : (const float4*)(x + base);
    float4* op = (float4*)(out + base);

    for (int i = threadIdx.x; i < PP / 4; i += 256) {
        float4 sv = sp[i];
        float4 rv = rp[i];
        float4 o;
        float t;
        t = fmaf(sv.x, sc, sh); o.x = t * fast_sigmoid(t) + fmaf(rv.x, a2, c2);
        t = fmaf(sv.y, sc, sh); o.y = t * fast_sigmoid(t) + fmaf(rv.y, a2, c2);
        t = fmaf(sv.z, sc, sh); o.z = t * fast_sigmoid(t) + fmaf(rv.z, a2, c2);
        t = fmaf(sv.w, sc, sh); o.w = t * fast_sigmoid(t) + fmaf(rv.w, a2, c2);
        op[i] = o;
    }
}

// ---------------- launch ----------------
extern "C" void kernel_launch(void* const* d_in, const int* in_sizes, int n_in,
                              void* d_out, int out_size) {
    const float* x        = (const float*)d_in[0];
    const float* weights  = (const float*)d_in[1];
    const int*   indices  = (const int*)d_in[2];
    const float* shared_w = (const float*)d_in[3];
    const float* bn_gamma = (const float*)d_in[4];
    const float* bn_beta  = (const float*)d_in[5];
    const float* w1       = (const float*)d_in[6];
    const float* g1       = (const float*)d_in[7];
    const float* b1       = (const float*)d_in[8];
    const float* w2       = (const float*)d_in[9];
    const float* g2       = (const float*)d_in[10];
    const float* b2       = (const float*)d_in[11];
    float* out = (float*)d_out;

    cudaFuncSetAttribute(k_convg1, cudaFuncAttributeMaxDynamicSharedMemorySize, SMEM_CONV);
    cudaFuncSetAttribute(k_gemm2, cudaFuncAttributeMaxDynamicSharedMemorySize, SMEM_G2);

    k_prep<<<3985, 256>>>(x, shared_w, w1, w2);
    k_convg1<<<dim3(53, 3, BB), NT, SMEM_CONV>>>(indices);    // conv + gemm1
    k_fin1<<<1, 256>>>(bn_gamma, bn_beta);
    k_gemm2<<<dim3(53, 1, BB), NT, SMEM_G2>>>(indices, g1, b1);
    k_fin_gn2<<<1, 128>>>();
    k_combine<<<BB * CC, 256>>>(x, weights, indices, g2, b2, out);
}